// round 15
// baseline (speedup 1.0000x reference)
#include <cuda_runtime.h>
#include <math.h>
#include <stdint.h>

#define BB 32
#define SS 128
#define UU 256
#define HH 128
#define VV 30001

// Scratch (__device__ globals: allocation-free rule)
__device__ float g_state[BB * UU * HH];   // per-(b,u) hidden state
__device__ float g_outs[BB * SS * HH];    // RNN outputs (tf32-rounded) = GEMM A

__device__ __forceinline__ float to_tf32(float x) {
    float r;
    asm("cvt.rna.tf32.f32 %0, %1;" : "=f"(r) : "f"(x));
    return r;
}

// f32x2 packed math (sm_103a)
__device__ __forceinline__ unsigned long long pack2(float lo, float hi) {
    unsigned long long d;
    asm("mov.b64 %0, {%1, %2};" : "=l"(d) : "f"(lo), "f"(hi));
    return d;
}
__device__ __forceinline__ void unpack2(unsigned long long v, float& lo, float& hi) {
    asm("mov.b64 {%0, %1}, %2;" : "=f"(lo), "=f"(hi) : "l"(v));
}
__device__ __forceinline__ void fma2(unsigned long long& d, unsigned long long a,
                                     unsigned long long b) {
    asm("fma.rn.f32x2 %0, %1, %2, %0;" : "+l"(d) : "l"(a), "l"(b));
}

// ---- MUFU-free transcendentals (FMA pipe only) ----
// exp(y) for y in [-34, 34]; rel err ~2.4e-6
__device__ __forceinline__ float fexp(float y) {
    float t = y * 1.4426950408889634f;     // y * log2(e)
    float n = rintf(t);
    float r = t - n;                        // [-0.5, 0.5]
    float p = 1.3333558e-3f;                // 2^r Taylor (ln2 powers / k!)
    p = fmaf(p, r, 9.6181291e-3f);
    p = fmaf(p, r, 5.5504109e-2f);
    p = fmaf(p, r, 2.4022650e-1f);
    p = fmaf(p, r, 6.9314718e-1f);
    p = fmaf(p, r, 1.0f);
    float s = __int_as_float(((int)n + 127) << 23);
    return p * s;
}
// 1/d for positive normal d; bit-hack seed + 3 Newton iters (err ~1e-8)
__device__ __forceinline__ float frcp_pos(float d) {
    float x = __uint_as_float(0x7EF311C3u - __float_as_uint(d));
    x = x * fmaf(-d, x, 2.0f);
    x = x * fmaf(-d, x, 2.0f);
    x = x * fmaf(-d, x, 2.0f);
    return x;
}
__device__ __forceinline__ float fsigmoid(float x) {   // x pre-clamped
    return frcp_pos(1.0f + fexp(-x));
}
__device__ __forceinline__ float ftanh_c(float x) {    // x pre-clamped
    float e = fexp(-2.0f * x);
    return (1.0f - e) * frcp_pos(1.0f + e);
}

// ===========================================================================
// RNN scan (structure unchanged from R14; activations now MUFU-free)
// ===========================================================================
#define CH 16
#define TP 20

#define RNN_F_WRU   (128 * 256)
#define RNN_F_WC    (128 * 128)
#define RNN_F_BUFS  (3 * 128 * TP)
#define RNN_INTS    (128 + 128 + 128 + 128 + 130 + 8)
#define RNN_SMEM_BYTES ((RNN_F_WRU + RNN_F_WC + 256 + 128 + RNN_F_BUFS + RNN_INTS) * 4)

__global__ __launch_bounds__(256, 1) void rnn_kernel(
    const int* __restrict__ users, const int* __restrict__ items,
    const float* __restrict__ h0,
    const float* __restrict__ P_ru, const float* __restrict__ W_ru,
    const float* __restrict__ b_ru, const float* __restrict__ P_c,
    const float* __restrict__ W_c,  const float* __restrict__ b_c)
{
    extern __shared__ float sm[];
    float* sWru = sm;
    float* sWc  = sWru + RNN_F_WRU;
    float* sbru = sWc + RNN_F_WC;
    float* sbc  = sbru + 256;
    float* sHT  = sbc + 128;
    float* sRHT = sHT + 128 * TP;
    float* sZT  = sRHT + 128 * TP;
    int*   su      = (int*)(sZT + 128 * TP);
    int*   sit     = su + 128;
    int*   slev    = sit + 128;
    int*   sorder  = slev + 128;
    int*   slstart = sorder + 128;
    int*   smisc   = slstart + 130;

    const int b   = blockIdx.x;
    const int tid = threadIdx.x;

    {
        const float4* s4 = (const float4*)W_ru;
        float4*       d4 = (float4*)sWru;
        for (int i = tid; i < RNN_F_WRU / 4; i += 256) d4[i] = s4[i];
        const float4* s4c = (const float4*)W_c;
        float4*       d4c = (float4*)sWc;
        for (int i = tid; i < RNN_F_WC / 4; i += 256) d4c[i] = s4c[i];
    }
    sbru[tid] = b_ru[tid];
    if (tid < HH) sbc[tid] = b_c[tid];

    for (int i = tid; i < 3 * 128 * TP; i += 256) sHT[i] = 0.0f;

    {
        const float4* src = (const float4*)(h0 + (size_t)b * UU * HH);
        float4*       dst = (float4*)(g_state + (size_t)b * UU * HH);
        for (int i = tid; i < UU * HH / 4; i += 256) dst[i] = src[i];
    }

    if (tid < SS) {
        su[tid]  = users[b * SS + tid];
        sit[tid] = items[b * SS + tid];
    }
    __syncthreads();

    if (tid < SS) {
        int u = su[tid], c = 0;
        for (int tp = 0; tp < tid; tp++) c += (su[tp] == u);
        slev[tid] = c;
    }
    __syncthreads();
    if (tid == 0) {
        int m = 0;
        for (int t = 0; t < SS; t++) m = max(m, slev[t]);
        smisc[0] = m + 1;
    }
    if (tid <= SS) {
        int c = 0;
        for (int t = 0; t < SS; t++) c += (slev[t] < tid);
        slstart[tid] = c;
    }
    __syncthreads();
    if (tid < SS) {
        int l = slev[tid], r = 0;
        for (int tp = 0; tp < tid; tp++) r += (slev[tp] == l);
        sorder[slstart[l] + r] = tid;
    }
    __syncthreads();

    const int maxlev = smisc[0];
    float* state_b = g_state + (size_t)b * UU * HH;
    float* out_b   = g_outs + (size_t)b * SS * HH;
    const int j = tid;

    for (int l = 0; l < maxlev; l++) {
        const int lstart = slstart[l], lend = slstart[l + 1];
        for (int cs = lstart; cs < lend; cs += CH) {
            const int n = min(CH, lend - cs);

            {
                int i      = tid & 15;
                int r4base = tid >> 4;
                if (i < n) {
                    int t = sorder[cs + i];
                    const float4* srcs = (const float4*)(state_b + su[t] * HH);
                    #pragma unroll
                    for (int rr = 0; rr < 2; rr++) {
                        int r4 = r4base + rr * 16;
                        float4 v = srcs[r4];
                        int k0 = r4 * 4;
                        sHT[(k0 + 0) * TP + i] = v.x;
                        sHT[(k0 + 1) * TP + i] = v.y;
                        sHT[(k0 + 2) * TP + i] = v.z;
                        sHT[(k0 + 3) * TP + i] = v.w;
                    }
                }
            }
            __syncthreads();

            {
                float pAdd[CH];
                #pragma unroll
                for (int i = 0; i < CH; i++) pAdd[i] = 0.0f;
                for (int i = 0; i < n; i++)
                    pAdd[i] = P_ru[(size_t)sit[sorder[cs + i]] * (2 * HH) + j];

                unsigned long long acc2[CH / 2];
                #pragma unroll
                for (int p = 0; p < CH / 2; p++) acc2[p] = 0ULL;

                #pragma unroll 4
                for (int k = 0; k < HH; k++) {
                    float w = sWru[k * 256 + j];
                    unsigned long long w2 = pack2(w, w);
                    const ulonglong2* h4 = (const ulonglong2*)(sHT + k * TP);
                    #pragma unroll
                    for (int q = 0; q < CH / 4; q++) {
                        ulonglong2 hp = h4[q];
                        fma2(acc2[2 * q],     hp.x, w2);
                        fma2(acc2[2 * q + 1], hp.y, w2);
                    }
                }

                float bj = sbru[j];
                if (j < HH) {
                    #pragma unroll
                    for (int p = 0; p < CH / 2; p++) {
                        float a0, a1;
                        unpack2(acc2[p], a0, a1);
                        float x0 = fminf(fmaxf(a0 + pAdd[2 * p] + bj,     -15.f), 15.f);
                        float x1 = fminf(fmaxf(a1 + pAdd[2 * p + 1] + bj, -15.f), 15.f);
                        float r0 = fsigmoid(x0);
                        float r1 = fsigmoid(x1);
                        sRHT[j * TP + 2 * p]     = r0 * sHT[j * TP + 2 * p];
                        sRHT[j * TP + 2 * p + 1] = r1 * sHT[j * TP + 2 * p + 1];
                    }
                } else {
                    int jz = j - HH;
                    #pragma unroll
                    for (int p = 0; p < CH / 2; p++) {
                        float a0, a1;
                        unpack2(acc2[p], a0, a1);
                        float x0 = fminf(fmaxf(a0 + pAdd[2 * p] + bj,     -15.f), 15.f);
                        float x1 = fminf(fmaxf(a1 + pAdd[2 * p + 1] + bj, -15.f), 15.f);
                        sZT[jz * TP + 2 * p]     = fsigmoid(x0);
                        sZT[jz * TP + 2 * p + 1] = fsigmoid(x1);
                    }
                }
            }
            __syncthreads();

            if (j < HH) {
                float pAdd[CH];
                #pragma unroll
                for (int i = 0; i < CH; i++) pAdd[i] = 0.0f;
                for (int i = 0; i < n; i++)
                    pAdd[i] = P_c[(size_t)sit[sorder[cs + i]] * HH + j];

                unsigned long long acc2[CH / 2];
                #pragma unroll
                for (int p = 0; p < CH / 2; p++) acc2[p] = 0ULL;

                #pragma unroll 4
                for (int k = 0; k < HH; k++) {
                    float w = sWc[k * 128 + j];
                    unsigned long long w2 = pack2(w, w);
                    const ulonglong2* r4 = (const ulonglong2*)(sRHT + k * TP);
                    #pragma unroll
                    for (int q = 0; q < CH / 4; q++) {
                        ulonglong2 rp = r4[q];
                        fma2(acc2[2 * q],     rp.x, w2);
                        fma2(acc2[2 * q + 1], rp.y, w2);
                    }
                }

                float bj = sbc[j];
                float cc[CH];
                #pragma unroll
                for (int p = 0; p < CH / 2; p++) {
                    float a0, a1;
                    unpack2(acc2[p], a0, a1);
                    float x0 = fminf(fmaxf(a0 + pAdd[2 * p] + bj,     -15.f), 15.f);
                    float x1 = fminf(fmaxf(a1 + pAdd[2 * p + 1] + bj, -15.f), 15.f);
                    cc[2 * p]     = ftanh_c(x0);
                    cc[2 * p + 1] = ftanh_c(x1);
                }
                for (int i = 0; i < n; i++) {
                    int t = sorder[cs + i];
                    float z = sZT[j * TP + i];
                    float h = sHT[j * TP + i];
                    float hn = z * h + (1.0f - z) * cc[i];
                    state_b[su[t] * HH + j] = hn;
                    out_b[(size_t)t * HH + j] = to_tf32(hn);
                }
            }
            __syncthreads();
        }
    }
}

// ===========================================================================
// Logits GEMM (unchanged from R14 passing version): mma.sync tf32,
// 2 CTAs/SM, 32x32 warp tiles, single-buffered 64m A overlapped w/ epilogue.
// ===========================================================================
#define MSUB   64
#define MSTRIP 512
#define NSUB   (MSTRIP / MSUB)
#define APITCH 132
#define G_NB2  (16 * 512)
#define G_A_FLOATS (MSUB * APITCH)
#define STPITCH 68
#define G_ST_F2 (16 * STPITCH)
#define G_SMEM_BYTES (G_NB2 * 8 + G_A_FLOATS * 4 + G_ST_F2 * 8)

__device__ __forceinline__ void cp_async16(uint32_t saddr, const void* gsrc) {
    asm volatile("cp.async.cg.shared.global [%0], [%1], 16;\n" :: "r"(saddr), "l"(gsrc));
}
__device__ __forceinline__ void cp_commit() { asm volatile("cp.async.commit_group;\n"); }
__device__ __forceinline__ void cp_wait0()  { asm volatile("cp.async.wait_group 0;\n"); }

__device__ __forceinline__ void mma_tf32(float c[4], const unsigned a[4],
                                         const unsigned bfr[2]) {
    asm volatile(
        "mma.sync.aligned.m16n8k8.row.col.f32.tf32.tf32.f32 "
        "{%0,%1,%2,%3}, {%4,%5,%6,%7}, {%8,%9}, {%0,%1,%2,%3};\n"
        : "+f"(c[0]), "+f"(c[1]), "+f"(c[2]), "+f"(c[3])
        : "r"(a[0]), "r"(a[1]), "r"(a[2]), "r"(a[3]), "r"(bfr[0]), "r"(bfr[1]));
}

__global__ __launch_bounds__(256, 2) void gemm_kernel(const float* __restrict__ ws,
                                                      float* __restrict__ out)
{
    extern __shared__ float smg[];
    float2* sBp = (float2*)smg;
    float*  sA  = smg + G_NB2 * 2;
    float2* sSt = (float2*)(sA + G_A_FLOATS);

    const int tid = threadIdx.x;
    const int n0  = blockIdx.x * 128;
    const int mg  = blockIdx.y * MSTRIP;

    uint32_t sA_base = (uint32_t)__cvta_generic_to_shared(sA);

    {
        const float* src = g_outs + (size_t)mg * HH;
        for (int idx = tid; idx < MSUB * 32; idx += 256) {
            int row = idx >> 5, q = idx & 31;
            cp_async16(sA_base + (row * APITCH + q * 4) * 4, src + row * HH + q * 4);
        }
        cp_commit();
    }

    for (int idx = tid; idx < 16 * 128 * 4; idx += 256) {
        int c   = idx & 127;
        int lcc = (idx >> 7) & 3;
        int ks  = idx >> 9;
        int k   = ks * 8 + lcc;
        int gn  = n0 + c;
        float v0 = 0.0f, v1 = 0.0f;
        if (gn < VV) {
            v0 = ws[(size_t)k * VV + gn];
            v1 = ws[(size_t)(k + 4) * VV + gn];
        }
        sBp[ks * 512 + c * 4 + lcc] = make_float2(to_tf32(v0), to_tf32(v1));
    }

    const int wid  = tid >> 5;
    const int lane = tid & 31;
    const int wm = (wid & 1) * 32;
    const int wn = (wid >> 1) * 32;
    const int lr = lane >> 2;
    const int lc = lane & 3;

    cp_wait0();
    __syncthreads();

    for (int msub = 0; msub < NSUB; msub++) {
        float acc[2][4][4];
        #pragma unroll
        for (int mt = 0; mt < 2; mt++)
            #pragma unroll
            for (int nt = 0; nt < 4; nt++)
                #pragma unroll
                for (int q = 0; q < 4; q++) acc[mt][nt][q] = 0.0f;

        #pragma unroll
        for (int ks = 0; ks < 16; ks++) {
            const int k0 = ks * 8;
            unsigned a[2][4];
            #pragma unroll
            for (int mt = 0; mt < 2; mt++) {
                int r = wm + mt * 16 + lr;
                a[mt][0] = __float_as_uint(sA[r * APITCH + k0 + lc]);
                a[mt][1] = __float_as_uint(sA[(r + 8) * APITCH + k0 + lc]);
                a[mt][2] = __float_as_uint(sA[r * APITCH + k0 + lc + 4]);
                a[mt][3] = __float_as_uint(sA[(r + 8) * APITCH + k0 + lc + 4]);
            }
            unsigned bfr[4][2];
            #pragma unroll
            for (int nt = 0; nt < 4; nt++) {
                int c = wn + nt * 8 + lr;
                float2 bp = sBp[ks * 512 + c * 4 + lc];
                bfr[nt][0] = __float_as_uint(bp.x);
                bfr[nt][1] = __float_as_uint(bp.y);
            }
            #pragma unroll
            for (int mt = 0; mt < 2; mt++)
                #pragma unroll
                for (int nt = 0; nt < 4; nt++)
                    mma_tf32(acc[mt][nt], a[mt], bfr[nt]);
        }

        __syncthreads();

        if (msub < NSUB - 1) {
            const float* src = g_outs + (size_t)(mg + (msub + 1) * MSUB) * HH;
            for (int idx = tid; idx < MSUB * 32; idx += 256) {
                int row = idx >> 5, q = idx & 31;
                cp_async16(sA_base + (row * APITCH + q * 4) * 4, src + row * HH + q * 4);
            }
            cp_commit();
        }

        const int m0 = mg + msub * MSUB;
        #pragma unroll
        for (int pass = 0; pass < 4; pass++) {
            const int pwm = (pass >> 1) * 32;
            const int pmt = pass & 1;
            if (wm == pwm) {
                #pragma unroll
                for (int nt = 0; nt < 4; nt++) {
                    int c2 = (wn >> 1) + nt * 4 + lc;
                    sSt[lr * STPITCH + c2]       = make_float2(acc[pmt][nt][0], acc[pmt][nt][1]);
                    sSt[(lr + 8) * STPITCH + c2] = make_float2(acc[pmt][nt][2], acc[pmt][nt][3]);
                }
            }
            __syncthreads();
            for (int idx = tid; idx < 16 * 128; idx += 256) {
                int row = idx >> 7, col = idx & 127;
                int gc = n0 + col;
                if (gc < VV) {
                    float v = ((const float*)(sSt + row * STPITCH))[col];
                    out[(size_t)(m0 + pass * 16 + row) * VV + gc] = v;
                }
            }
            __syncthreads();
        }

        cp_wait0();
        __syncthreads();
    }
}

// ---------------------------------------------------------------------------
// launch
// ---------------------------------------------------------------------------
extern "C" void kernel_launch(void* const* d_in, const int* in_sizes, int n_in,
                              void* d_out, int out_size)
{
    const int*   users = (const int*)d_in[0];
    const int*   items = (const int*)d_in[1];
    const float* h0    = (const float*)d_in[2];
    const float* P_ru  = (const float*)d_in[3];
    const float* W_ru  = (const float*)d_in[4];
    const float* b_ru  = (const float*)d_in[5];
    const float* P_c   = (const float*)d_in[6];
    const float* W_c   = (const float*)d_in[7];
    const float* b_c   = (const float*)d_in[8];
    const float* ws    = (const float*)d_in[9];
    float* out = (float*)d_out;

    static_assert(RNN_SMEM_BYTES <= 232448, "rnn smem too big");
    static_assert(G_SMEM_BYTES <= 116224, "gemm smem too big for 2 CTAs/SM");

    cudaFuncSetAttribute(rnn_kernel, cudaFuncAttributeMaxDynamicSharedMemorySize,
                         RNN_SMEM_BYTES);
    cudaFuncSetAttribute(gemm_kernel, cudaFuncAttributeMaxDynamicSharedMemorySize,
                         G_SMEM_BYTES);

    rnn_kernel<<<BB, 256, RNN_SMEM_BYTES>>>(users, items, h0, P_ru, W_ru, b_ru,
                                            P_c, W_c, b_c);

    dim3 grid((VV + 127) / 128, (BB * SS) / MSTRIP);
    gemm_kernel<<<grid, 256, G_SMEM_BYTES>>>(ws, out);
}